// round 3
// baseline (speedup 1.0000x reference)
#include <cuda_runtime.h>
#include <math.h>

// Problem constants
#define BB 2
#define TT 2048
#define EE 1024
#define HH 16
#define DD 64
#define BT (BB*TT)          // 4096

// Scratch (allocation-free rule: __device__ globals)
__device__ float g_vx[BB*TT*EE];   // value projection, (B*T, E)
__device__ float g_o [BB*TT*EE];   // attention output, (B*T, E)

// ---------------------------------------------------------------------------
// GEMM: C[M,N] = A[M,K] @ B[N,K]^T + bias[N]   (both row-major, K-contiguous)
// 128x128 block tile, BK=8, 256 threads, 8x8 per-thread microtile.
// ---------------------------------------------------------------------------
__global__ __launch_bounds__(256, 2)
void gemm_nt_bias(const float* __restrict__ A, const float* __restrict__ Bm,
                  const float* __restrict__ bias, float* __restrict__ C,
                  int M, int N, int K)
{
    __shared__ float As[8][128];
    __shared__ float Bs[8][128];

    const int tid  = threadIdx.x;
    const int row0 = blockIdx.y * 128;
    const int col0 = blockIdx.x * 128;
    const int tm   = tid >> 4;        // 0..15 (row group)
    const int tn   = tid & 15;        // 0..15 (col group)
    const int lr   = tid >> 1;        // 0..127 (load row)
    const int lc   = (tid & 1) << 2;  // 0 or 4 (load k offset)

    const float* Ag = A  + (size_t)(row0 + lr) * K + lc;
    const float* Bg = Bm + (size_t)(col0 + lr) * K + lc;

    float acc[8][8];
    #pragma unroll
    for (int i = 0; i < 8; i++)
        #pragma unroll
        for (int j = 0; j < 8; j++) acc[i][j] = 0.f;

    for (int k0 = 0; k0 < K; k0 += 8) {
        float4 a4 = *(const float4*)(Ag + k0);
        float4 b4 = *(const float4*)(Bg + k0);
        As[lc+0][lr] = a4.x; As[lc+1][lr] = a4.y; As[lc+2][lr] = a4.z; As[lc+3][lr] = a4.w;
        Bs[lc+0][lr] = b4.x; Bs[lc+1][lr] = b4.y; Bs[lc+2][lr] = b4.z; Bs[lc+3][lr] = b4.w;
        __syncthreads();

        #pragma unroll
        for (int kk = 0; kk < 8; kk++) {
            float4 a0 = *(const float4*)&As[kk][tm*4];
            float4 a1 = *(const float4*)&As[kk][64 + tm*4];
            float4 b0 = *(const float4*)&Bs[kk][tn*4];
            float4 b1 = *(const float4*)&Bs[kk][64 + tn*4];
            float a[8] = {a0.x,a0.y,a0.z,a0.w, a1.x,a1.y,a1.z,a1.w};
            float b[8] = {b0.x,b0.y,b0.z,b0.w, b1.x,b1.y,b1.z,b1.w};
            #pragma unroll
            for (int i = 0; i < 8; i++)
                #pragma unroll
                for (int j = 0; j < 8; j++)
                    acc[i][j] += a[i] * b[j];
        }
        __syncthreads();
    }

    // Epilogue: rows = {tm*4+ii, 64+tm*4+ii}, cols = {tn*4+jj, 64+tn*4+jj}
    #pragma unroll
    for (int i = 0; i < 8; i++) {
        int r = row0 + ((i < 4) ? (tm*4 + i) : (64 + tm*4 + (i - 4)));
        #pragma unroll
        for (int jh = 0; jh < 2; jh++) {
            int c = col0 + jh*64 + tn*4;
            float4 v;
            v.x = acc[i][jh*4+0] + bias[c+0];
            v.y = acc[i][jh*4+1] + bias[c+1];
            v.z = acc[i][jh*4+2] + bias[c+2];
            v.w = acc[i][jh*4+3] + bias[c+3];
            *(float4*)&C[(size_t)r * N + c] = v;
        }
    }
}

// ---------------------------------------------------------------------------
// Fused bilinear attention, flash-style.
// grid = (T/64 query tiles, B*H). 256 threads: thread (q = tid/4, tx = tid%4).
// Prologue computes Qs = (Xq @ W_h) * 0.125 (reusing K/V smem as staging).
// Mainloop: online softmax over 32 key tiles of 64.
// SMEM rows padded to 68 floats -> conflict-free broadcasts + float4 aligned.
// ---------------------------------------------------------------------------
#define PAD 68
#define ATTN_SMEM (4 * 64 * PAD * 4)   // Qs, Ks, Vs, Ps = 69632 B

__global__ __launch_bounds__(256)
void attn_kernel(const float* __restrict__ x, const float* __restrict__ w_att,
                 const float* __restrict__ vx, float* __restrict__ o)
{
    extern __shared__ float sm[];
    float* Qs = sm;
    float* Ks = sm + 64 * PAD;
    float* Vs = sm + 2 * 64 * PAD;
    float* Ps = sm + 3 * 64 * PAD;

    const int qt = blockIdx.x;          // query tile
    const int bh = blockIdx.y;          // b*H + h
    const int b  = bh >> 4;
    const int h  = bh & 15;
    const int tid = threadIdx.x;
    const int q  = tid >> 2;            // query row in tile, 0..63
    const int tx = tid & 3;

    const float* xb = x    + (size_t)b * TT * EE;
    const float* vb = vx   + (size_t)b * TT * EE;
    const int q0 = qt * 64;

    // ---- Prologue: stage Xq tile into Ks, W_h into Vs; compute Qs ----
    for (int idx = tid; idx < 64 * 16; idx += 256) {
        int r = idx >> 4;
        int f = (idx & 15) << 2;
        *(float4*)&Ks[r * PAD + f] = *(const float4*)&xb[(size_t)(q0 + r) * EE + h * DD + f];
        *(float4*)&Vs[r * PAD + f] = *(const float4*)&w_att[(size_t)(h * DD + r) * DD + f];
    }
    __syncthreads();
    {
        float4 aq[4] = {{0,0,0,0},{0,0,0,0},{0,0,0,0},{0,0,0,0}};
        #pragma unroll 8
        for (int d = 0; d < 64; d++) {
            float xd = Ks[q * PAD + d];
            #pragma unroll
            for (int c = 0; c < 4; c++) {
                float4 w4 = *(const float4*)&Vs[d * PAD + c*16 + tx*4];
                aq[c].x += xd * w4.x; aq[c].y += xd * w4.y;
                aq[c].z += xd * w4.z; aq[c].w += xd * w4.w;
            }
        }
        const float scale = 0.125f;   // 1/sqrt(64)
        #pragma unroll
        for (int c = 0; c < 4; c++) {
            float4 v; v.x = aq[c].x*scale; v.y = aq[c].y*scale;
                      v.z = aq[c].z*scale; v.w = aq[c].w*scale;
            *(float4*)&Qs[q * PAD + c*16 + tx*4] = v;
        }
    }

    // ---- Main loop ----
    float4 o4[4] = {{0,0,0,0},{0,0,0,0},{0,0,0,0},{0,0,0,0}};
    float m = -INFINITY, l = 0.f;

    for (int s0 = 0; s0 < TT; s0 += 64) {
        __syncthreads();   // previous-tile smem consumers done (also orders Qs)
        for (int idx = tid; idx < 64 * 16; idx += 256) {
            int r = idx >> 4;
            int f = (idx & 15) << 2;
            *(float4*)&Ks[r * PAD + f] = *(const float4*)&xb[(size_t)(s0 + r) * EE + h * DD + f];
            *(float4*)&Vs[r * PAD + f] = *(const float4*)&vb[(size_t)(s0 + r) * EE + h * DD + f];
        }
        __syncthreads();

        // scores: s[jj] for key j = jj*4 + tx
        float s[16];
        #pragma unroll
        for (int jj = 0; jj < 16; jj++) s[jj] = 0.f;
        #pragma unroll
        for (int d0 = 0; d0 < 64; d0 += 4) {
            float4 q4 = *(const float4*)&Qs[q * PAD + d0];
            #pragma unroll
            for (int jj = 0; jj < 16; jj++) {
                float4 k4 = *(const float4*)&Ks[(jj*4 + tx) * PAD + d0];
                s[jj] += q4.x*k4.x + q4.y*k4.y + q4.z*k4.z + q4.w*k4.w;
            }
        }

        // online softmax bookkeeping (replicated across the 4-lane row group)
        float mt = s[0];
        #pragma unroll
        for (int jj = 1; jj < 16; jj++) mt = fmaxf(mt, s[jj]);
        mt = fmaxf(mt, __shfl_xor_sync(0xffffffffu, mt, 1));
        mt = fmaxf(mt, __shfl_xor_sync(0xffffffffu, mt, 2));
        float mnew = fmaxf(m, mt);
        float corr = __expf(m - mnew);
        m = mnew;

        float lsum = 0.f;
        #pragma unroll
        for (int jj = 0; jj < 16; jj++) {
            float p = __expf(s[jj] - mnew);
            lsum += p;
            Ps[q * PAD + jj*4 + tx] = p;
        }
        lsum += __shfl_xor_sync(0xffffffffu, lsum, 1);
        lsum += __shfl_xor_sync(0xffffffffu, lsum, 2);
        l = l * corr + lsum;

        #pragma unroll
        for (int c = 0; c < 4; c++) {
            o4[c].x *= corr; o4[c].y *= corr; o4[c].z *= corr; o4[c].w *= corr;
        }
        __syncwarp();

        // PV accumulate: o[q][dd] += sum_j P[q][j] * V[j][dd]
        #pragma unroll
        for (int j = 0; j < 64; j++) {
            float pj = Ps[q * PAD + j];
            #pragma unroll
            for (int c = 0; c < 4; c++) {
                float4 v4 = *(const float4*)&Vs[j * PAD + c*16 + tx*4];
                o4[c].x += pj * v4.x; o4[c].y += pj * v4.y;
                o4[c].z += pj * v4.z; o4[c].w += pj * v4.w;
            }
        }
    }

    // ---- Epilogue: normalize + write o in (B,T,E) layout ----
    float inv = 1.f / l;
    float* ob = o + (size_t)b * TT * EE + (size_t)(q0 + q) * EE + h * DD;
    #pragma unroll
    for (int c = 0; c < 4; c++) {
        float4 v; v.x = o4[c].x*inv; v.y = o4[c].y*inv;
                  v.z = o4[c].z*inv; v.w = o4[c].w*inv;
        *(float4*)&ob[c*16 + tx*4] = v;
    }
}

// ---------------------------------------------------------------------------
// Launch
// ---------------------------------------------------------------------------
extern "C" void kernel_launch(void* const* d_in, const int* in_sizes, int n_in,
                              void* d_out, int out_size)
{
    (void)in_sizes; (void)n_in; (void)out_size;
    const float* x      = (const float*)d_in[0];  // (B,T,E)
    const float* w_att  = (const float*)d_in[1];  // (H,D,D)
    const float* wv_w   = (const float*)d_in[2];  // (E,E)
    const float* wv_b   = (const float*)d_in[3];  // (E,)
    const float* out_w  = (const float*)d_in[4];  // (E,E)
    const float* out_b  = (const float*)d_in[5];  // (E,)
    float* out = (float*)d_out;                   // (B,T,E)

    float *vxp = nullptr, *op = nullptr;
    cudaGetSymbolAddress((void**)&vxp, g_vx);
    cudaGetSymbolAddress((void**)&op,  g_o);

    cudaFuncSetAttribute(attn_kernel,
                         cudaFuncAttributeMaxDynamicSharedMemorySize, ATTN_SMEM);

    // 1) value projection: vx = x @ wv_w^T + wv_b
    gemm_nt_bias<<<dim3(EE/128, BT/128), 256>>>(x, wv_w, wv_b, vxp, BT, EE, EE);

    // 2) fused bilinear attention (computes x_h @ W_h internally)
    attn_kernel<<<dim3(TT/64, BB*HH), 256, ATTN_SMEM>>>(x, w_att, vxp, op);

    // 3) output projection: out = o @ out_w^T + out_b
    gemm_nt_bias<<<dim3(EE/128, BT/128), 256>>>(op, out_w, out_b, out, BT, EE, EE);
}

// round 4
// speedup vs baseline: 1.0006x; 1.0006x over previous
#include <cuda_runtime.h>
#include <math.h>

// Problem constants
#define BB 2
#define TT 2048
#define EE 1024
#define HH 16
#define DD 64
#define BT (BB*TT)          // 4096

// Scratch (allocation-free rule: __device__ globals)
__device__ float g_vx[BB*TT*EE];   // value projection, (B*T, E)
__device__ float g_o [BB*TT*EE];   // attention output, (B*T, E)

// ---------------------------------------------------------------------------
// GEMM: C[M,N] = A[M,K] @ B[N,K]^T + bias[N]   (both row-major, K-contiguous)
// 128x128 block tile, BK=8, 256 threads, 8x8 per-thread microtile.
// ---------------------------------------------------------------------------
__global__ __launch_bounds__(256, 2)
void gemm_nt_bias(const float* __restrict__ A, const float* __restrict__ Bm,
                  const float* __restrict__ bias, float* __restrict__ C,
                  int M, int N, int K)
{
    __shared__ float As[8][128];
    __shared__ float Bs[8][128];

    const int tid  = threadIdx.x;
    const int row0 = blockIdx.y * 128;
    const int col0 = blockIdx.x * 128;
    const int tm   = tid >> 4;        // 0..15 (row group)
    const int tn   = tid & 15;        // 0..15 (col group)
    const int lr   = tid >> 1;        // 0..127 (load row)
    const int lc   = (tid & 1) << 2;  // 0 or 4 (load k offset)

    const float* Ag = A  + (size_t)(row0 + lr) * K + lc;
    const float* Bg = Bm + (size_t)(col0 + lr) * K + lc;

    float acc[8][8];
    #pragma unroll
    for (int i = 0; i < 8; i++)
        #pragma unroll
        for (int j = 0; j < 8; j++) acc[i][j] = 0.f;

    for (int k0 = 0; k0 < K; k0 += 8) {
        float4 a4 = *(const float4*)(Ag + k0);
        float4 b4 = *(const float4*)(Bg + k0);
        As[lc+0][lr] = a4.x; As[lc+1][lr] = a4.y; As[lc+2][lr] = a4.z; As[lc+3][lr] = a4.w;
        Bs[lc+0][lr] = b4.x; Bs[lc+1][lr] = b4.y; Bs[lc+2][lr] = b4.z; Bs[lc+3][lr] = b4.w;
        __syncthreads();

        #pragma unroll
        for (int kk = 0; kk < 8; kk++) {
            float4 a0 = *(const float4*)&As[kk][tm*4];
            float4 a1 = *(const float4*)&As[kk][64 + tm*4];
            float4 b0 = *(const float4*)&Bs[kk][tn*4];
            float4 b1 = *(const float4*)&Bs[kk][64 + tn*4];
            float a[8] = {a0.x,a0.y,a0.z,a0.w, a1.x,a1.y,a1.z,a1.w};
            float b[8] = {b0.x,b0.y,b0.z,b0.w, b1.x,b1.y,b1.z,b1.w};
            #pragma unroll
            for (int i = 0; i < 8; i++)
                #pragma unroll
                for (int j = 0; j < 8; j++)
                    acc[i][j] += a[i] * b[j];
        }
        __syncthreads();
    }

    // Epilogue: rows = {tm*4+ii, 64+tm*4+ii}, cols = {tn*4+jj, 64+tn*4+jj}
    #pragma unroll
    for (int i = 0; i < 8; i++) {
        int r = row0 + ((i < 4) ? (tm*4 + i) : (64 + tm*4 + (i - 4)));
        #pragma unroll
        for (int jh = 0; jh < 2; jh++) {
            int c = col0 + jh*64 + tn*4;
            float4 v;
            v.x = acc[i][jh*4+0] + bias[c+0];
            v.y = acc[i][jh*4+1] + bias[c+1];
            v.z = acc[i][jh*4+2] + bias[c+2];
            v.w = acc[i][jh*4+3] + bias[c+3];
            *(float4*)&C[(size_t)r * N + c] = v;
        }
    }
}

// ---------------------------------------------------------------------------
// Fused bilinear attention, flash-style.
// grid = (T/64 query tiles, B*H). 256 threads: thread (q = tid/4, tx = tid%4).
// Prologue computes Qs = (Xq @ W_h) * 0.125 (reusing K/V smem as staging).
// Mainloop: online softmax over 32 key tiles of 64.
// SMEM rows padded to 68 floats -> conflict-free broadcasts + float4 aligned.
// ---------------------------------------------------------------------------
#define PAD 68
#define ATTN_SMEM (4 * 64 * PAD * 4)   // Qs, Ks, Vs, Ps = 69632 B

__global__ __launch_bounds__(256)
void attn_kernel(const float* __restrict__ x, const float* __restrict__ w_att,
                 const float* __restrict__ vx, float* __restrict__ o)
{
    extern __shared__ float sm[];
    float* Qs = sm;
    float* Ks = sm + 64 * PAD;
    float* Vs = sm + 2 * 64 * PAD;
    float* Ps = sm + 3 * 64 * PAD;

    const int qt = blockIdx.x;          // query tile
    const int bh = blockIdx.y;          // b*H + h
    const int b  = bh >> 4;
    const int h  = bh & 15;
    const int tid = threadIdx.x;
    const int q  = tid >> 2;            // query row in tile, 0..63
    const int tx = tid & 3;

    const float* xb = x    + (size_t)b * TT * EE;
    const float* vb = vx   + (size_t)b * TT * EE;
    const int q0 = qt * 64;

    // ---- Prologue: stage Xq tile into Ks, W_h into Vs; compute Qs ----
    for (int idx = tid; idx < 64 * 16; idx += 256) {
        int r = idx >> 4;
        int f = (idx & 15) << 2;
        *(float4*)&Ks[r * PAD + f] = *(const float4*)&xb[(size_t)(q0 + r) * EE + h * DD + f];
        *(float4*)&Vs[r * PAD + f] = *(const float4*)&w_att[(size_t)(h * DD + r) * DD + f];
    }
    __syncthreads();
    {
        float4 aq[4] = {{0,0,0,0},{0,0,0,0},{0,0,0,0},{0,0,0,0}};
        #pragma unroll 8
        for (int d = 0; d < 64; d++) {
            float xd = Ks[q * PAD + d];
            #pragma unroll
            for (int c = 0; c < 4; c++) {
                float4 w4 = *(const float4*)&Vs[d * PAD + c*16 + tx*4];
                aq[c].x += xd * w4.x; aq[c].y += xd * w4.y;
                aq[c].z += xd * w4.z; aq[c].w += xd * w4.w;
            }
        }
        const float scale = 0.125f;   // 1/sqrt(64)
        #pragma unroll
        for (int c = 0; c < 4; c++) {
            float4 v; v.x = aq[c].x*scale; v.y = aq[c].y*scale;
                      v.z = aq[c].z*scale; v.w = aq[c].w*scale;
            *(float4*)&Qs[q * PAD + c*16 + tx*4] = v;
        }
    }

    // ---- Main loop ----
    float4 o4[4] = {{0,0,0,0},{0,0,0,0},{0,0,0,0},{0,0,0,0}};
    float m = -INFINITY, l = 0.f;

    for (int s0 = 0; s0 < TT; s0 += 64) {
        __syncthreads();   // previous-tile smem consumers done (also orders Qs)
        for (int idx = tid; idx < 64 * 16; idx += 256) {
            int r = idx >> 4;
            int f = (idx & 15) << 2;
            *(float4*)&Ks[r * PAD + f] = *(const float4*)&xb[(size_t)(s0 + r) * EE + h * DD + f];
            *(float4*)&Vs[r * PAD + f] = *(const float4*)&vb[(size_t)(s0 + r) * EE + h * DD + f];
        }
        __syncthreads();

        // scores: s[jj] for key j = jj*4 + tx
        float s[16];
        #pragma unroll
        for (int jj = 0; jj < 16; jj++) s[jj] = 0.f;
        #pragma unroll
        for (int d0 = 0; d0 < 64; d0 += 4) {
            float4 q4 = *(const float4*)&Qs[q * PAD + d0];
            #pragma unroll
            for (int jj = 0; jj < 16; jj++) {
                float4 k4 = *(const float4*)&Ks[(jj*4 + tx) * PAD + d0];
                s[jj] += q4.x*k4.x + q4.y*k4.y + q4.z*k4.z + q4.w*k4.w;
            }
        }

        // online softmax bookkeeping (replicated across the 4-lane row group)
        float mt = s[0];
        #pragma unroll
        for (int jj = 1; jj < 16; jj++) mt = fmaxf(mt, s[jj]);
        mt = fmaxf(mt, __shfl_xor_sync(0xffffffffu, mt, 1));
        mt = fmaxf(mt, __shfl_xor_sync(0xffffffffu, mt, 2));
        float mnew = fmaxf(m, mt);
        float corr = __expf(m - mnew);
        m = mnew;

        float lsum = 0.f;
        #pragma unroll
        for (int jj = 0; jj < 16; jj++) {
            float p = __expf(s[jj] - mnew);
            lsum += p;
            Ps[q * PAD + jj*4 + tx] = p;
        }
        lsum += __shfl_xor_sync(0xffffffffu, lsum, 1);
        lsum += __shfl_xor_sync(0xffffffffu, lsum, 2);
        l = l * corr + lsum;

        #pragma unroll
        for (int c = 0; c < 4; c++) {
            o4[c].x *= corr; o4[c].y *= corr; o4[c].z *= corr; o4[c].w *= corr;
        }
        __syncwarp();

        // PV accumulate: o[q][dd] += sum_j P[q][j] * V[j][dd]
        #pragma unroll
        for (int j = 0; j < 64; j++) {
            float pj = Ps[q * PAD + j];
            #pragma unroll
            for (int c = 0; c < 4; c++) {
                float4 v4 = *(const float4*)&Vs[j * PAD + c*16 + tx*4];
                o4[c].x += pj * v4.x; o4[c].y += pj * v4.y;
                o4[c].z += pj * v4.z; o4[c].w += pj * v4.w;
            }
        }
    }

    // ---- Epilogue: normalize + write o in (B,T,E) layout ----
    float inv = 1.f / l;
    float* ob = o + (size_t)b * TT * EE + (size_t)(q0 + q) * EE + h * DD;
    #pragma unroll
    for (int c = 0; c < 4; c++) {
        float4 v; v.x = o4[c].x*inv; v.y = o4[c].y*inv;
                  v.z = o4[c].z*inv; v.w = o4[c].w*inv;
        *(float4*)&ob[c*16 + tx*4] = v;
    }
}

// ---------------------------------------------------------------------------
// Launch
// ---------------------------------------------------------------------------
extern "C" void kernel_launch(void* const* d_in, const int* in_sizes, int n_in,
                              void* d_out, int out_size)
{
    (void)in_sizes; (void)n_in; (void)out_size;
    const float* x      = (const float*)d_in[0];  // (B,T,E)
    const float* w_att  = (const float*)d_in[1];  // (H,D,D)
    const float* wv_w   = (const float*)d_in[2];  // (E,E)
    const float* wv_b   = (const float*)d_in[3];  // (E,)
    const float* out_w  = (const float*)d_in[4];  // (E,E)
    const float* out_b  = (const float*)d_in[5];  // (E,)
    float* out = (float*)d_out;                   // (B,T,E)

    float *vxp = nullptr, *op = nullptr;
    cudaGetSymbolAddress((void**)&vxp, g_vx);
    cudaGetSymbolAddress((void**)&op,  g_o);

    cudaFuncSetAttribute(attn_kernel,
                         cudaFuncAttributeMaxDynamicSharedMemorySize, ATTN_SMEM);

    // 1) value projection: vx = x @ wv_w^T + wv_b
    gemm_nt_bias<<<dim3(EE/128, BT/128), 256>>>(x, wv_w, wv_b, vxp, BT, EE, EE);

    // 2) fused bilinear attention (computes x_h @ W_h internally)
    attn_kernel<<<dim3(TT/64, BB*HH), 256, ATTN_SMEM>>>(x, w_att, vxp, op);

    // 3) output projection: out = o @ out_w^T + out_b
    gemm_nt_bias<<<dim3(EE/128, BT/128), 256>>>(op, out_w, out_b, out, BT, EE, EE);
}

// round 5
// speedup vs baseline: 1.0032x; 1.0025x over previous
#include <cuda_runtime.h>
#include <math.h>

// Problem constants
#define BB 2
#define TT 2048
#define EE 1024
#define HH 16
#define DD 64
#define BT (BB*TT)          // 4096

// Scratch (allocation-free rule: __device__ globals)
__device__ float g_vx[BB*TT*EE];   // value projection, (B*T, E)
__device__ float g_o [BB*TT*EE];   // attention output, (B*T, E)

// ---------------------------------------------------------------------------
// GEMM: C[M,N] = A[M,K] @ B[N,K]^T + bias[N]   (both row-major, K-contiguous)
// 128x128 block tile, BK=8, 256 threads, 8x8 per-thread microtile.
// ---------------------------------------------------------------------------
__global__ __launch_bounds__(256, 2)
void gemm_nt_bias(const float* __restrict__ A, const float* __restrict__ Bm,
                  const float* __restrict__ bias, float* __restrict__ C,
                  int M, int N, int K)
{
    __shared__ float As[8][128];
    __shared__ float Bs[8][128];

    const int tid  = threadIdx.x;
    const int row0 = blockIdx.y * 128;
    const int col0 = blockIdx.x * 128;
    const int tm   = tid >> 4;        // 0..15 (row group)
    const int tn   = tid & 15;        // 0..15 (col group)
    const int lr   = tid >> 1;        // 0..127 (load row)
    const int lc   = (tid & 1) << 2;  // 0 or 4 (load k offset)

    const float* Ag = A  + (size_t)(row0 + lr) * K + lc;
    const float* Bg = Bm + (size_t)(col0 + lr) * K + lc;

    float acc[8][8];
    #pragma unroll
    for (int i = 0; i < 8; i++)
        #pragma unroll
        for (int j = 0; j < 8; j++) acc[i][j] = 0.f;

    for (int k0 = 0; k0 < K; k0 += 8) {
        float4 a4 = *(const float4*)(Ag + k0);
        float4 b4 = *(const float4*)(Bg + k0);
        As[lc+0][lr] = a4.x; As[lc+1][lr] = a4.y; As[lc+2][lr] = a4.z; As[lc+3][lr] = a4.w;
        Bs[lc+0][lr] = b4.x; Bs[lc+1][lr] = b4.y; Bs[lc+2][lr] = b4.z; Bs[lc+3][lr] = b4.w;
        __syncthreads();

        #pragma unroll
        for (int kk = 0; kk < 8; kk++) {
            float4 a0 = *(const float4*)&As[kk][tm*4];
            float4 a1 = *(const float4*)&As[kk][64 + tm*4];
            float4 b0 = *(const float4*)&Bs[kk][tn*4];
            float4 b1 = *(const float4*)&Bs[kk][64 + tn*4];
            float a[8] = {a0.x,a0.y,a0.z,a0.w, a1.x,a1.y,a1.z,a1.w};
            float b[8] = {b0.x,b0.y,b0.z,b0.w, b1.x,b1.y,b1.z,b1.w};
            #pragma unroll
            for (int i = 0; i < 8; i++)
                #pragma unroll
                for (int j = 0; j < 8; j++)
                    acc[i][j] += a[i] * b[j];
        }
        __syncthreads();
    }

    // Epilogue: rows = {tm*4+ii, 64+tm*4+ii}, cols = {tn*4+jj, 64+tn*4+jj}
    #pragma unroll
    for (int i = 0; i < 8; i++) {
        int r = row0 + ((i < 4) ? (tm*4 + i) : (64 + tm*4 + (i - 4)));
        #pragma unroll
        for (int jh = 0; jh < 2; jh++) {
            int c = col0 + jh*64 + tn*4;
            float4 v;
            v.x = acc[i][jh*4+0] + bias[c+0];
            v.y = acc[i][jh*4+1] + bias[c+1];
            v.z = acc[i][jh*4+2] + bias[c+2];
            v.w = acc[i][jh*4+3] + bias[c+3];
            *(float4*)&C[(size_t)r * N + c] = v;
        }
    }
}

// ---------------------------------------------------------------------------
// Fused bilinear attention, flash-style.
// grid = (T/64 query tiles, B*H). 256 threads: thread (q = tid/4, tx = tid%4).
// Prologue computes Qs = (Xq @ W_h) * 0.125 (reusing K/V smem as staging).
// Mainloop: online softmax over 32 key tiles of 64.
// SMEM rows padded to 68 floats -> conflict-free broadcasts + float4 aligned.
// ---------------------------------------------------------------------------
#define PAD 68
#define ATTN_SMEM (4 * 64 * PAD * 4)   // Qs, Ks, Vs, Ps = 69632 B

__global__ __launch_bounds__(256)
void attn_kernel(const float* __restrict__ x, const float* __restrict__ w_att,
                 const float* __restrict__ vx, float* __restrict__ o)
{
    extern __shared__ float sm[];
    float* Qs = sm;
    float* Ks = sm + 64 * PAD;
    float* Vs = sm + 2 * 64 * PAD;
    float* Ps = sm + 3 * 64 * PAD;

    const int qt = blockIdx.x;          // query tile
    const int bh = blockIdx.y;          // b*H + h
    const int b  = bh >> 4;
    const int h  = bh & 15;
    const int tid = threadIdx.x;
    const int q  = tid >> 2;            // query row in tile, 0..63
    const int tx = tid & 3;

    const float* xb = x    + (size_t)b * TT * EE;
    const float* vb = vx   + (size_t)b * TT * EE;
    const int q0 = qt * 64;

    // ---- Prologue: stage Xq tile into Ks, W_h into Vs; compute Qs ----
    for (int idx = tid; idx < 64 * 16; idx += 256) {
        int r = idx >> 4;
        int f = (idx & 15) << 2;
        *(float4*)&Ks[r * PAD + f] = *(const float4*)&xb[(size_t)(q0 + r) * EE + h * DD + f];
        *(float4*)&Vs[r * PAD + f] = *(const float4*)&w_att[(size_t)(h * DD + r) * DD + f];
    }
    __syncthreads();
    {
        float4 aq[4] = {{0,0,0,0},{0,0,0,0},{0,0,0,0},{0,0,0,0}};
        #pragma unroll 8
        for (int d = 0; d < 64; d++) {
            float xd = Ks[q * PAD + d];
            #pragma unroll
            for (int c = 0; c < 4; c++) {
                float4 w4 = *(const float4*)&Vs[d * PAD + c*16 + tx*4];
                aq[c].x += xd * w4.x; aq[c].y += xd * w4.y;
                aq[c].z += xd * w4.z; aq[c].w += xd * w4.w;
            }
        }
        const float scale = 0.125f;   // 1/sqrt(64)
        #pragma unroll
        for (int c = 0; c < 4; c++) {
            float4 v; v.x = aq[c].x*scale; v.y = aq[c].y*scale;
                      v.z = aq[c].z*scale; v.w = aq[c].w*scale;
            *(float4*)&Qs[q * PAD + c*16 + tx*4] = v;
        }
    }

    // ---- Main loop ----
    float4 o4[4] = {{0,0,0,0},{0,0,0,0},{0,0,0,0},{0,0,0,0}};
    float m = -INFINITY, l = 0.f;

    for (int s0 = 0; s0 < TT; s0 += 64) {
        __syncthreads();   // previous-tile smem consumers done (also orders Qs)
        for (int idx = tid; idx < 64 * 16; idx += 256) {
            int r = idx >> 4;
            int f = (idx & 15) << 2;
            *(float4*)&Ks[r * PAD + f] = *(const float4*)&xb[(size_t)(s0 + r) * EE + h * DD + f];
            *(float4*)&Vs[r * PAD + f] = *(const float4*)&vb[(size_t)(s0 + r) * EE + h * DD + f];
        }
        __syncthreads();

        // scores: s[jj] for key j = jj*4 + tx
        float s[16];
        #pragma unroll
        for (int jj = 0; jj < 16; jj++) s[jj] = 0.f;
        #pragma unroll
        for (int d0 = 0; d0 < 64; d0 += 4) {
            float4 q4 = *(const float4*)&Qs[q * PAD + d0];
            #pragma unroll
            for (int jj = 0; jj < 16; jj++) {
                float4 k4 = *(const float4*)&Ks[(jj*4 + tx) * PAD + d0];
                s[jj] += q4.x*k4.x + q4.y*k4.y + q4.z*k4.z + q4.w*k4.w;
            }
        }

        // online softmax bookkeeping (replicated across the 4-lane row group)
        float mt = s[0];
        #pragma unroll
        for (int jj = 1; jj < 16; jj++) mt = fmaxf(mt, s[jj]);
        mt = fmaxf(mt, __shfl_xor_sync(0xffffffffu, mt, 1));
        mt = fmaxf(mt, __shfl_xor_sync(0xffffffffu, mt, 2));
        float mnew = fmaxf(m, mt);
        float corr = __expf(m - mnew);
        m = mnew;

        float lsum = 0.f;
        #pragma unroll
        for (int jj = 0; jj < 16; jj++) {
            float p = __expf(s[jj] - mnew);
            lsum += p;
            Ps[q * PAD + jj*4 + tx] = p;
        }
        lsum += __shfl_xor_sync(0xffffffffu, lsum, 1);
        lsum += __shfl_xor_sync(0xffffffffu, lsum, 2);
        l = l * corr + lsum;

        #pragma unroll
        for (int c = 0; c < 4; c++) {
            o4[c].x *= corr; o4[c].y *= corr; o4[c].z *= corr; o4[c].w *= corr;
        }
        __syncwarp();

        // PV accumulate: o[q][dd] += sum_j P[q][j] * V[j][dd]
        #pragma unroll
        for (int j = 0; j < 64; j++) {
            float pj = Ps[q * PAD + j];
            #pragma unroll
            for (int c = 0; c < 4; c++) {
                float4 v4 = *(const float4*)&Vs[j * PAD + c*16 + tx*4];
                o4[c].x += pj * v4.x; o4[c].y += pj * v4.y;
                o4[c].z += pj * v4.z; o4[c].w += pj * v4.w;
            }
        }
    }

    // ---- Epilogue: normalize + write o in (B,T,E) layout ----
    float inv = 1.f / l;
    float* ob = o + (size_t)b * TT * EE + (size_t)(q0 + q) * EE + h * DD;
    #pragma unroll
    for (int c = 0; c < 4; c++) {
        float4 v; v.x = o4[c].x*inv; v.y = o4[c].y*inv;
                  v.z = o4[c].z*inv; v.w = o4[c].w*inv;
        *(float4*)&ob[c*16 + tx*4] = v;
    }
}

// ---------------------------------------------------------------------------
// Launch
// ---------------------------------------------------------------------------
extern "C" void kernel_launch(void* const* d_in, const int* in_sizes, int n_in,
                              void* d_out, int out_size)
{
    (void)in_sizes; (void)n_in; (void)out_size;
    const float* x      = (const float*)d_in[0];  // (B,T,E)
    const float* w_att  = (const float*)d_in[1];  // (H,D,D)
    const float* wv_w   = (const float*)d_in[2];  // (E,E)
    const float* wv_b   = (const float*)d_in[3];  // (E,)
    const float* out_w  = (const float*)d_in[4];  // (E,E)
    const float* out_b  = (const float*)d_in[5];  // (E,)
    float* out = (float*)d_out;                   // (B,T,E)

    float *vxp = nullptr, *op = nullptr;
    cudaGetSymbolAddress((void**)&vxp, g_vx);
    cudaGetSymbolAddress((void**)&op,  g_o);

    cudaFuncSetAttribute(attn_kernel,
                         cudaFuncAttributeMaxDynamicSharedMemorySize, ATTN_SMEM);

    // 1) value projection: vx = x @ wv_w^T + wv_b
    gemm_nt_bias<<<dim3(EE/128, BT/128), 256>>>(x, wv_w, wv_b, vxp, BT, EE, EE);

    // 2) fused bilinear attention (computes x_h @ W_h internally)
    attn_kernel<<<dim3(TT/64, BB*HH), 256, ATTN_SMEM>>>(x, w_att, vxp, op);

    // 3) output projection: out = o @ out_w^T + out_b
    gemm_nt_bias<<<dim3(EE/128, BT/128), 256>>>(op, out_w, out_b, out, BT, EE, EE);
}